// round 8
// baseline (speedup 1.0000x reference)
#include <cuda_runtime.h>
#include <cuda_fp16.h>
#include <cstdint>
#include <cstddef>

// ============================================================================
// out = sparse @ W + b via 2:4 structured-sparse fp16 mma.sp (m16n8k32).
// 90% random sparsity -> 99.63% of 4-groups have <=2 nonzeros; extras go to
// deterministic overflow lists, applied as fp32 rank-1 corrections afterward.
// Metadata layout (selector 0): lane 4q+h (h in {0,1}) holds, for the 16-row
// block: bits[0:16) = row q, bits[16:32) = row q+8, covering k-groups
// h*4..h*4+3 of the k32 chunk (4 bits per group, idx0 | idx1<<2, idx0<idx1).
// R8: force 2 CTAs/SM on the GEMM (reg cap 128) to cover per-kt barrier
// bubbles; corr_kernel re-parallelized (block per row, coalesced RMW).
// ============================================================================

#define MDIM 4096
#define NDIM 4096
#define KDIM 4096

#define BM 128
#define BN 128
#define BKD 64                       // dense K per pipeline step
#define STAGES 4
#define NKT (KDIM / BKD)             // 64
#define NC32 (KDIM / 32)             // 128 k32 chunks
#define NRB (MDIM / 16)              // 256 16-row blocks
#define A_ST 8192                    // 128 rows x 32 compressed halves (64B rows)
#define B_ST 16384                   // 128 rows x 64 halves (128B rows)
#define STAGE_BYTES 25600            // A_ST + B_ST + 1KB meta, 1KB-aligned
#define SMEM_TOTAL (STAGES * STAGE_BYTES) // 102400 -> 2 CTAs/SM

struct OvfEnt { uint32_t k; float v; };

// Packed operands
__device__ __align__(16) __half   g_Av[(size_t)MDIM * (KDIM / 2)];  // compressed A
__device__ __align__(16) uint16_t g_meta16[(size_t)NC32 * NRB * 16 * 2]; // frag layout
__device__ __align__(16) __half   g_B[(size_t)NDIM * KDIM];         // W^T fp16
__device__ __align__(16) OvfEnt   g_ovf[(size_t)MDIM * 128 * 8];
__device__            uint8_t     g_cnt[(size_t)MDIM * 128];

// ---------------------------------------------------------------------------
__device__ __forceinline__ uint32_t h2_as_u32(__half2 h) {
    return *reinterpret_cast<uint32_t*>(&h);
}
__device__ __forceinline__ uint32_t smem_u32(const void* p) {
    uint32_t a;
    asm("{ .reg .u64 t; cvta.to.shared.u64 t, %1; cvt.u32.u64 %0, t; }" : "=r"(a) : "l"(p));
    return a;
}
__device__ __forceinline__ void cp_async16(uint32_t dst, const void* src) {
    asm volatile("cp.async.cg.shared.global [%0], [%1], 16;" :: "r"(dst), "l"(src));
}

#define LDSM_X4(r, addr)                                                         \
    asm volatile("ldmatrix.sync.aligned.m8n8.x4.shared.b16 {%0,%1,%2,%3}, [%4];" \
                 : "=r"((r)[0]), "=r"((r)[1]), "=r"((r)[2]), "=r"((r)[3])        \
                 : "r"(addr))

__device__ __forceinline__ void mma_sp(float* c, const uint32_t* a, uint32_t b0,
                                       uint32_t b1, uint32_t b2, uint32_t b3,
                                       uint32_t e) {
    asm volatile(
        "mma.sp::ordered_metadata.sync.aligned.m16n8k32.row.col.f32.f16.f16.f32 "
        "{%0,%1,%2,%3}, {%4,%5,%6,%7}, {%8,%9,%10,%11}, {%0,%1,%2,%3}, %12, 0x0;"
        : "+f"(c[0]), "+f"(c[1]), "+f"(c[2]), "+f"(c[3])
        : "r"(a[0]), "r"(a[1]), "r"(a[2]), "r"(a[3]),
          "r"(b0), "r"(b1), "r"(b2), "r"(b3), "r"(e));
}

// ---------------------------------------------------------------------------
// pack_x_sparse: thread per (row, k32 chunk). Emits 16 compressed halves,
// metadata in sp-fragment layout (two 16-bit scattered stores), overflow
// entries at deterministic per-chunk slots (no atomics).
// ---------------------------------------------------------------------------
__global__ void pack_x_sparse(const float* __restrict__ x) {
    int t = blockIdx.x * 256 + threadIdx.x;   // 524288 threads
    int row = t >> 7, chunk = t & 127;
    const float* src = x + (size_t)row * KDIM + chunk * 32;

    float vals[16];
    uint32_t meta = 0;
    OvfEnt ov[8];
    int no = 0;

#pragma unroll
    for (int g = 0; g < 8; ++g) {
        float4 q = *reinterpret_cast<const float4*>(src + g * 4);
        float v[4] = {q.x, q.y, q.z, q.w};
        int i0 = -1, i1 = -1;
#pragma unroll
        for (int p = 0; p < 4; ++p) {
            if (v[p] != 0.0f) {
                if (i0 < 0) i0 = p;
                else if (i1 < 0) i1 = p;
                else if (no < 8) { ov[no].k = chunk * 32 + g * 4 + p; ov[no].v = v[p]; ++no; }
            }
        }
        if (i0 < 0) { i0 = 0; i1 = 1; }
        else if (i1 < 0) {
            if (i0 < 3) i1 = i0 + 1;
            else { i0 = 2; i1 = 3; }   // value at 2 is zero, keeps order
        }
        vals[2 * g]     = v[i0];
        vals[2 * g + 1] = v[i1];
        meta |= (uint32_t)(i0 | (i1 << 2)) << (4 * g);
    }

    // compressed values: 16 halves = 32B
    uint32_t h[8];
#pragma unroll
    for (int j = 0; j < 8; ++j)
        h[j] = h2_as_u32(__floats2half2_rn(vals[2 * j], vals[2 * j + 1]));
    __half* dst = &g_Av[(size_t)row * (KDIM / 2) + chunk * 16];
    *reinterpret_cast<uint4*>(dst)     = make_uint4(h[0], h[1], h[2], h[3]);
    *reinterpret_cast<uint4*>(dst + 8) = make_uint4(h[4], h[5], h[6], h[7]);

    // metadata -> fragment layout. word index (q*2+h), half = (row>>3)&1.
    {
        int rb = row >> 4, q = row & 7, part = (row >> 3) & 1;
        size_t base = (((size_t)chunk * NRB + rb) * 16 + q * 2) * 2 + part;
        g_meta16[base]     = (uint16_t)(meta & 0xFFFF);   // h=0: k-groups 0-3
        g_meta16[base + 2] = (uint16_t)(meta >> 16);      // h=1: k-groups 4-7
    }

    // overflow
    g_cnt[(size_t)row * 128 + chunk] = (uint8_t)no;
    OvfEnt* oslot = &g_ovf[((size_t)row * 128 + chunk) * 8];
    for (int s = 0; s < no; ++s) oslot[s] = ov[s];
}

// ---------------------------------------------------------------------------
// pack_w: fp32 W[K][N] -> fp16 g_B[N][K] (transpose + convert).
// ---------------------------------------------------------------------------
__global__ void pack_w_kernel(const float* __restrict__ w) {
    __shared__ float tile[64][65];
    int nb = blockIdx.x >> 6, kb = blockIdx.x & 63;
    int tid = threadIdx.x;
#pragma unroll
    for (int i = 0; i < 16; ++i) {
        int lin = tid + i * 256;
        int kk = lin >> 6, nn = lin & 63;
        tile[kk][nn] = w[(size_t)(kb * 64 + kk) * NDIM + (nb * 64 + nn)];
    }
    __syncthreads();
    int nn = tid >> 2;
    int kq = (tid & 3) * 16;
    __half* dst = &g_B[(size_t)(nb * 64 + nn) * KDIM + kb * 64 + kq];
    uint32_t r[8];
#pragma unroll
    for (int j = 0; j < 8; ++j)
        r[j] = h2_as_u32(__floats2half2_rn(tile[kq + 2 * j][nn], tile[kq + 2 * j + 1][nn]));
    *reinterpret_cast<uint4*>(dst)     = make_uint4(r[0], r[1], r[2], r[3]);
    *reinterpret_cast<uint4*>(dst + 8) = make_uint4(r[4], r[5], r[6], r[7]);
}

// ---------------------------------------------------------------------------
// GEMM: 128x128 tile per CTA, dense-K 64 per step, 4-stage cp.async pipeline.
// A rows 64B (4x16B chunks, swz ch^((row>>1)&3)); B rows 128B (8 chunks,
// swz ch^(row&7)); meta per stage: [chunk(2)][rb_local(8)][16 words] = 1KB.
// ---------------------------------------------------------------------------
__device__ __forceinline__ void load_stage(uint32_t sb, int stage, int bm, int bn,
                                           int tid, int kt) {
    uint32_t aT = sb + stage * STAGE_BYTES;
    uint32_t bT = aT + A_ST;
    uint32_t mT = aT + A_ST + B_ST;

    // A: 512 cp16
    {
        int row = tid & 127;
        int c0 = (tid >> 7) * 2;
        const char* src = (const char*)&g_Av[(size_t)(bm * BM + row) * (KDIM / 2)] + kt * 64;
        int swz = (row >> 1) & 3;
#pragma unroll
        for (int j = 0; j < 2; ++j) {
            int c = c0 + j;
            cp_async16(aT + row * 64 + ((c ^ swz) * 16), src + c * 16);
        }
    }
    // B: 1024 cp16
    {
        int row = tid >> 1;
        int c0 = (tid & 1) * 4;
        const char* src = (const char*)&g_B[(size_t)(bn * BN + row) * KDIM] + kt * 128;
        int swz = row & 7;
#pragma unroll
        for (int j = 0; j < 4; ++j) {
            int c = c0 + j;
            cp_async16(bT + row * 128 + ((c ^ swz) * 16), src + c * 16);
        }
    }
    // meta: 64 cp16 (2 chunks x 8 rb x 64B)
    if (tid < 64) {
        int cl = tid >> 5;                // chunk local
        int rbl = (tid >> 2) & 7;         // rb local
        int w4 = tid & 3;                 // 4-word group
        const char* src = (const char*)&g_meta16[
            (((size_t)(kt * 2 + cl) * NRB + bm * 8 + rbl) * 16 + w4 * 4) * 2];
        cp_async16(mT + cl * 512 + rbl * 64 + w4 * 16, src);
    }
}

__global__ void __launch_bounds__(256, 2)
gemm_kernel(const float* __restrict__ bias, float* __restrict__ out) {
    extern __shared__ unsigned char smem[];
    const uint32_t sb = smem_u32(smem);
    const int tid = threadIdx.x, wid = tid >> 5, lane = tid & 31;
    const int bm = blockIdx.x & 31, bn = blockIdx.x >> 5;
    const int wm = (wid >> 2) * 64, wn = (wid & 3) * 32;

#pragma unroll
    for (int s = 0; s < STAGES - 1; ++s) {
        load_stage(sb, s, bm, bn, tid, s);
        asm volatile("cp.async.commit_group;" ::: "memory");
    }

    float c[4][4][4];
#pragma unroll
    for (int i = 0; i < 4; ++i)
#pragma unroll
        for (int j = 0; j < 4; ++j)
#pragma unroll
            for (int k = 0; k < 4; ++k) c[i][j][k] = 0.f;

    const int a_row = wm + (lane & 15);                      // + mi*16
    const int a_kh = lane >> 4;                              // 16B chunk parity
    const int b_row = wn + (lane & 7) + ((lane >> 4) << 3);  // + njb*16
    const int b_kh = (lane >> 3) & 1;
    const int m_word = ((lane >> 2) * 2 + (lane & 1)) * 4;   // meta word byte off
    const int rb0 = (wid >> 2) * 4;                          // + mi

    for (int kt = 0; kt < NKT; ++kt) {
        const int stage = kt & (STAGES - 1);
        asm volatile("cp.async.wait_group %0;" :: "n"(STAGES - 2) : "memory");
        __syncthreads();
        if (kt + STAGES - 1 < NKT)
            load_stage(sb, (kt + STAGES - 1) & (STAGES - 1), bm, bn, tid, kt + STAGES - 1);
        asm volatile("cp.async.commit_group;" ::: "memory");

        const uint32_t aT = sb + stage * STAGE_BYTES;
        const uint32_t bT = aT + A_ST;
        const uint32_t mT = aT + A_ST + B_ST;

#pragma unroll
        for (int chunk = 0; chunk < 2; ++chunk) {   // k32 each
            // metadata: one word per (mi); lanes %4 in {2,3} mirror {0,1}
            uint32_t e[4];
#pragma unroll
            for (int mi = 0; mi < 4; ++mi)
                asm volatile("ld.shared.b32 %0, [%1];"
                             : "=r"(e[mi])
                             : "r"(mT + chunk * 512 + (rb0 + mi) * 64 + m_word));
            // A compressed fragments
            uint32_t a[4][4];
#pragma unroll
            for (int mi = 0; mi < 4; ++mi) {
                int row = a_row + mi * 16;
                int ch = chunk * 2 + a_kh;
                uint32_t addr = aT + row * 64 + ((ch ^ ((row >> 1) & 3)) * 16);
                LDSM_X4(a[mi], addr);
            }
            // B fragments: 2 n16-blocks x 2 k16-halves
            uint32_t b[2][2][4];  // [njb][half][reg]
#pragma unroll
            for (int njb = 0; njb < 2; ++njb)
#pragma unroll
                for (int h = 0; h < 2; ++h) {
                    int row = b_row + njb * 16;
                    int ch = (chunk * 2 + h) * 2 + b_kh;
                    uint32_t addr = bT + row * 128 + ((ch ^ (row & 7)) * 16);
                    LDSM_X4(b[njb][h], addr);
                }
#pragma unroll
            for (int mi = 0; mi < 4; ++mi)
#pragma unroll
                for (int ni = 0; ni < 4; ++ni) {
                    int njb = ni >> 1, sub = (ni & 1) * 2;
                    mma_sp(c[mi][ni], a[mi],
                           b[njb][0][sub], b[njb][0][sub + 1],
                           b[njb][1][sub], b[njb][1][sub + 1], e[mi]);
                }
        }
    }

    // Epilogue: add bias, store fp32.
    const int g = lane >> 2, t2 = (lane & 3) * 2;
#pragma unroll
    for (int mi = 0; mi < 4; ++mi) {
        const int m = bm * BM + wm + mi * 16 + g;
#pragma unroll
        for (int ni = 0; ni < 4; ++ni) {
            const int n = bn * BN + wn + ni * 8 + t2;
            const float b0 = bias[n], b1 = bias[n + 1];
            float2 v0 = {c[mi][ni][0] + b0, c[mi][ni][1] + b1};
            float2 v1 = {c[mi][ni][2] + b0, c[mi][ni][3] + b1};
            *reinterpret_cast<float2*>(out + (size_t)m * NDIM + n) = v0;
            *reinterpret_cast<float2*>(out + (size_t)(m + 8) * NDIM + n) = v1;
        }
    }
}

// ---------------------------------------------------------------------------
// Correction: out[m,:] += sum over overflow entries v * W[k,:], fp32 exact.
// One BLOCK per row: warp 0 gathers the row's overflow list into SMEM, then
// all 256 threads RMW 16 contiguous columns each (coalesced out and W).
// ---------------------------------------------------------------------------
__global__ void __launch_bounds__(256)
corr_kernel(const float* __restrict__ w, float* __restrict__ out) {
    __shared__ uint32_t sk[64];
    __shared__ float sv[64];
    __shared__ int stot;
    const int m = blockIdx.x;
    const int tid = threadIdx.x, lane = tid & 31;

    if (tid < 32) {
        uint32_t cbytes = *(const uint32_t*)(g_cnt + (size_t)m * 128 + lane * 4);
        int local = (cbytes & 0xFF) + ((cbytes >> 8) & 0xFF) + ((cbytes >> 16) & 0xFF) +
                    (cbytes >> 24);
        int pre = local;
#pragma unroll
        for (int off = 1; off < 32; off <<= 1) {
            int nval = __shfl_up_sync(0xFFFFFFFFu, pre, off);
            if (lane >= off) pre += nval;
        }
        int excl = pre - local;
        int total = __shfl_sync(0xFFFFFFFFu, pre, 31);
        if (total > 64) total = 64;  // safety cap (probability ~0)
        if (local) {
            int pos = excl;
            for (int j = 0; j < 4; ++j) {
                int cc = (cbytes >> (8 * j)) & 0xFF;
                const OvfEnt* e = &g_ovf[((size_t)m * 128 + lane * 4 + j) * 8];
                for (int s = 0; s < cc && pos < 64; ++s, ++pos) {
                    sk[pos] = e[s].k;
                    sv[pos] = e[s].v;
                }
            }
        }
        if (lane == 31) stot = total;
    }
    __syncthreads();
    const int total = stot;
    if (!total) return;

    const int n0 = tid * 16;   // 256 threads x 16 cols = 4096
    float* orow = out + (size_t)m * NDIM + n0;
    float4 o[4];
#pragma unroll
    for (int j = 0; j < 4; ++j) o[j] = *reinterpret_cast<float4*>(orow + j * 4);
    for (int ei = 0; ei < total; ++ei) {
        const uint32_t k = sk[ei];
        const float v = sv[ei];
        const float* wr = w + (size_t)k * NDIM + n0;
#pragma unroll
        for (int j = 0; j < 4; ++j) {
            float4 ww = *reinterpret_cast<const float4*>(wr + j * 4);
            o[j].x += v * ww.x; o[j].y += v * ww.y;
            o[j].z += v * ww.z; o[j].w += v * ww.w;
        }
    }
#pragma unroll
    for (int j = 0; j < 4; ++j) *reinterpret_cast<float4*>(orow + j * 4) = o[j];
}

// ---------------------------------------------------------------------------
extern "C" void kernel_launch(void* const* d_in, const int* in_sizes, int n_in,
                              void* d_out, int out_size) {
    const float* x = (const float*)d_in[0];  // sparse [4096,4096]
    const float* w = (const float*)d_in[1];  // weight [4096,4096] (in,out)
    const float* b = (const float*)d_in[2];  // bias [4096]
    float* out = (float*)d_out;

    cudaFuncSetAttribute(gemm_kernel, cudaFuncAttributeMaxDynamicSharedMemorySize,
                         SMEM_TOTAL);

    pack_x_sparse<<<(MDIM * 128) / 256, 256>>>(x);
    pack_w_kernel<<<(KDIM / 64) * (NDIM / 64), 256>>>(w);
    gemm_kernel<<<(MDIM / BM) * (NDIM / BN), 256, SMEM_TOTAL>>>(b, out);
    corr_kernel<<<MDIM, 256>>>(w, out);
}

// round 9
// speedup vs baseline: 1.4643x; 1.4643x over previous
#include <cuda_runtime.h>
#include <cuda_fp16.h>
#include <cstdint>
#include <cstddef>

// ============================================================================
// out = sparse @ W + b via 2:4 structured-sparse fp16 mma.sp (m16n8k32).
// Overflow (>2 nz per 4-group, ~0.37%) -> exact fp32 rank-1 corrections.
// Metadata (selector 0): lane 4q+h holds rows q (lo16) / q+8 (hi16),
// k-groups h*4..h*4+3 of the k32 chunk.
// R9: 128x64 CTA tile -> ~80 regs -> 2 CTAs/SM naturally (covers barrier
// bubbles without spills); corr_kernel truly coalesced.
// ============================================================================

#define MDIM 4096
#define NDIM 4096
#define KDIM 4096

#define BM 128
#define BN 64
#define STAGES 4
#define NKT (KDIM / 64)              // 64 k-chunks of 64
#define NC32 (KDIM / 32)             // 128
#define NRB (MDIM / 16)              // 256
#define A_ST 8192                    // 128 rows x 64B (32 compressed halves)
#define B_ST 8192                    // 64 rows x 128B
#define STAGE_BYTES 17408            // A + B + 1KB meta
#define SMEM_TOTAL (STAGES * STAGE_BYTES) // 69632 -> 2 CTAs/SM

struct OvfEnt { uint32_t k; float v; };

__device__ __align__(16) __half   g_Av[(size_t)MDIM * (KDIM / 2)];
__device__ __align__(16) uint16_t g_meta16[(size_t)NC32 * NRB * 16 * 2];
__device__ __align__(16) __half   g_B[(size_t)NDIM * KDIM];
__device__ __align__(16) OvfEnt   g_ovf[(size_t)MDIM * 128 * 8];
__device__            uint8_t     g_cnt[(size_t)MDIM * 128];

// ---------------------------------------------------------------------------
__device__ __forceinline__ uint32_t h2_as_u32(__half2 h) {
    return *reinterpret_cast<uint32_t*>(&h);
}
__device__ __forceinline__ uint32_t smem_u32(const void* p) {
    uint32_t a;
    asm("{ .reg .u64 t; cvta.to.shared.u64 t, %1; cvt.u32.u64 %0, t; }" : "=r"(a) : "l"(p));
    return a;
}
__device__ __forceinline__ void cp_async16(uint32_t dst, const void* src) {
    asm volatile("cp.async.cg.shared.global [%0], [%1], 16;" :: "r"(dst), "l"(src));
}

#define LDSM_X4(r, addr)                                                         \
    asm volatile("ldmatrix.sync.aligned.m8n8.x4.shared.b16 {%0,%1,%2,%3}, [%4];" \
                 : "=r"((r)[0]), "=r"((r)[1]), "=r"((r)[2]), "=r"((r)[3])        \
                 : "r"(addr))

__device__ __forceinline__ void mma_sp(float* c, const uint32_t* a, uint32_t b0,
                                       uint32_t b1, uint32_t b2, uint32_t b3,
                                       uint32_t e) {
    asm volatile(
        "mma.sp::ordered_metadata.sync.aligned.m16n8k32.row.col.f32.f16.f16.f32 "
        "{%0,%1,%2,%3}, {%4,%5,%6,%7}, {%8,%9,%10,%11}, {%0,%1,%2,%3}, %12, 0x0;"
        : "+f"(c[0]), "+f"(c[1]), "+f"(c[2]), "+f"(c[3])
        : "r"(a[0]), "r"(a[1]), "r"(a[2]), "r"(a[3]),
          "r"(b0), "r"(b1), "r"(b2), "r"(b3), "r"(e));
}

// ---------------------------------------------------------------------------
// pack_x_sparse (unchanged from R7, known-good)
// ---------------------------------------------------------------------------
__global__ void pack_x_sparse(const float* __restrict__ x) {
    int t = blockIdx.x * 256 + threadIdx.x;
    int row = t >> 7, chunk = t & 127;
    const float* src = x + (size_t)row * KDIM + chunk * 32;

    float vals[16];
    uint32_t meta = 0;
    OvfEnt ov[8];
    int no = 0;

#pragma unroll
    for (int g = 0; g < 8; ++g) {
        float4 q = *reinterpret_cast<const float4*>(src + g * 4);
        float v[4] = {q.x, q.y, q.z, q.w};
        int i0 = -1, i1 = -1;
#pragma unroll
        for (int p = 0; p < 4; ++p) {
            if (v[p] != 0.0f) {
                if (i0 < 0) i0 = p;
                else if (i1 < 0) i1 = p;
                else if (no < 8) { ov[no].k = chunk * 32 + g * 4 + p; ov[no].v = v[p]; ++no; }
            }
        }
        if (i0 < 0) { i0 = 0; i1 = 1; }
        else if (i1 < 0) {
            if (i0 < 3) i1 = i0 + 1;
            else { i0 = 2; i1 = 3; }
        }
        vals[2 * g]     = v[i0];
        vals[2 * g + 1] = v[i1];
        meta |= (uint32_t)(i0 | (i1 << 2)) << (4 * g);
    }

    uint32_t h[8];
#pragma unroll
    for (int j = 0; j < 8; ++j)
        h[j] = h2_as_u32(__floats2half2_rn(vals[2 * j], vals[2 * j + 1]));
    __half* dst = &g_Av[(size_t)row * (KDIM / 2) + chunk * 16];
    *reinterpret_cast<uint4*>(dst)     = make_uint4(h[0], h[1], h[2], h[3]);
    *reinterpret_cast<uint4*>(dst + 8) = make_uint4(h[4], h[5], h[6], h[7]);

    {
        int rb = row >> 4, q = row & 7, part = (row >> 3) & 1;
        size_t base = (((size_t)chunk * NRB + rb) * 16 + q * 2) * 2 + part;
        g_meta16[base]     = (uint16_t)(meta & 0xFFFF);
        g_meta16[base + 2] = (uint16_t)(meta >> 16);
    }

    g_cnt[(size_t)row * 128 + chunk] = (uint8_t)no;
    OvfEnt* oslot = &g_ovf[((size_t)row * 128 + chunk) * 8];
    for (int s = 0; s < no; ++s) oslot[s] = ov[s];
}

// ---------------------------------------------------------------------------
// pack_w (unchanged)
// ---------------------------------------------------------------------------
__global__ void pack_w_kernel(const float* __restrict__ w) {
    __shared__ float tile[64][65];
    int nb = blockIdx.x >> 6, kb = blockIdx.x & 63;
    int tid = threadIdx.x;
#pragma unroll
    for (int i = 0; i < 16; ++i) {
        int lin = tid + i * 256;
        int kk = lin >> 6, nn = lin & 63;
        tile[kk][nn] = w[(size_t)(kb * 64 + kk) * NDIM + (nb * 64 + nn)];
    }
    __syncthreads();
    int nn = tid >> 2;
    int kq = (tid & 3) * 16;
    __half* dst = &g_B[(size_t)(nb * 64 + nn) * KDIM + kb * 64 + kq];
    uint32_t r[8];
#pragma unroll
    for (int j = 0; j < 8; ++j)
        r[j] = h2_as_u32(__floats2half2_rn(tile[kq + 2 * j][nn], tile[kq + 2 * j + 1][nn]));
    *reinterpret_cast<uint4*>(dst)     = make_uint4(r[0], r[1], r[2], r[3]);
    *reinterpret_cast<uint4*>(dst + 8) = make_uint4(r[4], r[5], r[6], r[7]);
}

// ---------------------------------------------------------------------------
// GEMM: 128x64 CTA tile, 8 warps (4 m-bands x 2 n-bands of 32x32), k64/step,
// 4-stage cp.async pipeline, 2 CTAs/SM.
// A rows 64B (4 chunks, swz ch^((row>>1)&3)); B rows 128B (8 chunks,
// swz ch^(row&7)); meta [chunk(2)][rb(8)][16 words] = 1KB/stage.
// ---------------------------------------------------------------------------
__device__ __forceinline__ void load_stage(uint32_t sb, int stage, int bm, int bn,
                                           int tid, int kt) {
    uint32_t aT = sb + stage * STAGE_BYTES;
    uint32_t bT = aT + A_ST;
    uint32_t mT = aT + A_ST + B_ST;

    // A: 512 cp16 (128 rows x 4 chunks)
    {
        int row = tid & 127;
        int c0 = (tid >> 7) * 2;
        const char* src = (const char*)&g_Av[(size_t)(bm * BM + row) * (KDIM / 2)] + kt * 64;
        int swz = (row >> 1) & 3;
#pragma unroll
        for (int j = 0; j < 2; ++j) {
            int c = c0 + j;
            cp_async16(aT + row * 64 + ((c ^ swz) * 16), src + c * 16);
        }
    }
    // B: 512 cp16 (64 rows x 8 chunks)
    {
        int row = tid >> 2;
        int c0 = (tid & 3) * 2;
        const char* src = (const char*)&g_B[(size_t)(bn * BN + row) * KDIM] + kt * 128;
        int swz = row & 7;
#pragma unroll
        for (int j = 0; j < 2; ++j) {
            int c = c0 + j;
            cp_async16(bT + row * 128 + ((c ^ swz) * 16), src + c * 16);
        }
    }
    // meta: 64 cp16
    if (tid < 64) {
        int cl = tid >> 5;
        int rbl = (tid >> 2) & 7;
        int w4 = tid & 3;
        const char* src = (const char*)&g_meta16[
            (((size_t)(kt * 2 + cl) * NRB + bm * 8 + rbl) * 16 + w4 * 4) * 2];
        cp_async16(mT + cl * 512 + rbl * 64 + w4 * 16, src);
    }
}

__global__ void __launch_bounds__(256, 2)
gemm_kernel(const float* __restrict__ bias, float* __restrict__ out) {
    extern __shared__ unsigned char smem[];
    const uint32_t sb = smem_u32(smem);
    const int tid = threadIdx.x, wid = tid >> 5, lane = tid & 31;
    const int bm = blockIdx.x & 31, bn = blockIdx.x >> 5;
    const int wm = (wid >> 1) * 32, wn = (wid & 1) * 32;

#pragma unroll
    for (int s = 0; s < STAGES - 1; ++s) {
        load_stage(sb, s, bm, bn, tid, s);
        asm volatile("cp.async.commit_group;" ::: "memory");
    }

    float c[2][4][4];
#pragma unroll
    for (int i = 0; i < 2; ++i)
#pragma unroll
        for (int j = 0; j < 4; ++j)
#pragma unroll
            for (int k = 0; k < 4; ++k) c[i][j][k] = 0.f;

    const int a_row = wm + (lane & 15);                      // + mi*16
    const int a_kh = lane >> 4;
    const int b_row = wn + (lane & 7) + ((lane >> 4) << 3);  // + njb*16
    const int b_kh = (lane >> 3) & 1;
    const int m_word = ((lane >> 2) * 2 + (lane & 1)) * 4;
    const int rb0 = (wid >> 1) * 2;                          // + mi

    for (int kt = 0; kt < NKT; ++kt) {
        const int stage = kt & (STAGES - 1);
        asm volatile("cp.async.wait_group %0;" :: "n"(STAGES - 2) : "memory");
        __syncthreads();
        if (kt + STAGES - 1 < NKT)
            load_stage(sb, (kt + STAGES - 1) & (STAGES - 1), bm, bn, tid, kt + STAGES - 1);
        asm volatile("cp.async.commit_group;" ::: "memory");

        const uint32_t aT = sb + stage * STAGE_BYTES;
        const uint32_t bT = aT + A_ST;
        const uint32_t mT = aT + A_ST + B_ST;

#pragma unroll
        for (int chunk = 0; chunk < 2; ++chunk) {
            uint32_t e[2];
#pragma unroll
            for (int mi = 0; mi < 2; ++mi)
                asm volatile("ld.shared.b32 %0, [%1];"
                             : "=r"(e[mi])
                             : "r"(mT + chunk * 512 + (rb0 + mi) * 64 + m_word));
            uint32_t a[2][4];
#pragma unroll
            for (int mi = 0; mi < 2; ++mi) {
                int row = a_row + mi * 16;
                int ch = chunk * 2 + a_kh;
                uint32_t addr = aT + row * 64 + ((ch ^ ((row >> 1) & 3)) * 16);
                LDSM_X4(a[mi], addr);
            }
            uint32_t b[2][2][4];  // [njb][half][reg]
#pragma unroll
            for (int njb = 0; njb < 2; ++njb)
#pragma unroll
                for (int h = 0; h < 2; ++h) {
                    int row = b_row + njb * 16;
                    int ch = (chunk * 2 + h) * 2 + b_kh;
                    uint32_t addr = bT + row * 128 + ((ch ^ (row & 7)) * 16);
                    LDSM_X4(b[njb][h], addr);
                }
#pragma unroll
            for (int mi = 0; mi < 2; ++mi)
#pragma unroll
                for (int ni = 0; ni < 4; ++ni) {
                    int njb = ni >> 1, sub = (ni & 1) * 2;
                    mma_sp(c[mi][ni], a[mi],
                           b[njb][0][sub], b[njb][0][sub + 1],
                           b[njb][1][sub], b[njb][1][sub + 1], e[mi]);
                }
        }
    }

    // Epilogue
    const int g = lane >> 2, t2 = (lane & 3) * 2;
#pragma unroll
    for (int mi = 0; mi < 2; ++mi) {
        const int m = bm * BM + wm + mi * 16 + g;
#pragma unroll
        for (int ni = 0; ni < 4; ++ni) {
            const int n = bn * BN + wn + ni * 8 + t2;
            const float b0 = bias[n], b1 = bias[n + 1];
            float2 v0 = {c[mi][ni][0] + b0, c[mi][ni][1] + b1};
            float2 v1 = {c[mi][ni][2] + b0, c[mi][ni][3] + b1};
            *reinterpret_cast<float2*>(out + (size_t)m * NDIM + n) = v0;
            *reinterpret_cast<float2*>(out + (size_t)(m + 8) * NDIM + n) = v1;
        }
    }
}

// ---------------------------------------------------------------------------
// Correction: block per row; warp 0 gathers overflow list; all 256 threads
// RMW with warp-contiguous float4 accesses (n = tid*4 + j*1024).
// ---------------------------------------------------------------------------
__global__ void __launch_bounds__(256)
corr_kernel(const float* __restrict__ w, float* __restrict__ out) {
    __shared__ uint32_t sk[64];
    __shared__ float sv[64];
    __shared__ int stot;
    const int m = blockIdx.x;
    const int tid = threadIdx.x, lane = tid & 31;

    if (tid < 32) {
        uint32_t cbytes = *(const uint32_t*)(g_cnt + (size_t)m * 128 + lane * 4);
        int local = (cbytes & 0xFF) + ((cbytes >> 8) & 0xFF) + ((cbytes >> 16) & 0xFF) +
                    (cbytes >> 24);
        int pre = local;
#pragma unroll
        for (int off = 1; off < 32; off <<= 1) {
            int nval = __shfl_up_sync(0xFFFFFFFFu, pre, off);
            if (lane >= off) pre += nval;
        }
        int excl = pre - local;
        int total = __shfl_sync(0xFFFFFFFFu, pre, 31);
        if (total > 64) total = 64;
        if (local) {
            int pos = excl;
            for (int j = 0; j < 4; ++j) {
                int cc = (cbytes >> (8 * j)) & 0xFF;
                const OvfEnt* e = &g_ovf[((size_t)m * 128 + lane * 4 + j) * 8];
                for (int s = 0; s < cc && pos < 64; ++s, ++pos) {
                    sk[pos] = e[s].k;
                    sv[pos] = e[s].v;
                }
            }
        }
        if (lane == 31) stot = total;
    }
    __syncthreads();
    const int total = stot;
    if (!total) return;

    float4 o[4];
#pragma unroll
    for (int j = 0; j < 4; ++j)
        o[j] = *reinterpret_cast<float4*>(out + (size_t)m * NDIM + tid * 4 + j * 1024);
    for (int ei = 0; ei < total; ++ei) {
        const uint32_t k = sk[ei];
        const float v = sv[ei];
        const float* wr = w + (size_t)k * NDIM;
#pragma unroll
        for (int j = 0; j < 4; ++j) {
            float4 ww = *reinterpret_cast<const float4*>(wr + tid * 4 + j * 1024);
            o[j].x += v * ww.x; o[j].y += v * ww.y;
            o[j].z += v * ww.z; o[j].w += v * ww.w;
        }
    }
#pragma unroll
    for (int j = 0; j < 4; ++j)
        *reinterpret_cast<float4*>(out + (size_t)m * NDIM + tid * 4 + j * 1024) = o[j];
}

// ---------------------------------------------------------------------------
extern "C" void kernel_launch(void* const* d_in, const int* in_sizes, int n_in,
                              void* d_out, int out_size) {
    const float* x = (const float*)d_in[0];
    const float* w = (const float*)d_in[1];
    const float* b = (const float*)d_in[2];
    float* out = (float*)d_out;

    cudaFuncSetAttribute(gemm_kernel, cudaFuncAttributeMaxDynamicSharedMemorySize,
                         SMEM_TOTAL);

    pack_x_sparse<<<(MDIM * 128) / 256, 256>>>(x);
    pack_w_kernel<<<(KDIM / 64) * (NDIM / 64), 256>>>(w);
    gemm_kernel<<<(MDIM / BM) * (NDIM / BN), 256, SMEM_TOTAL>>>(b, out);
    corr_kernel<<<MDIM, 256>>>(w, out);
}

// round 11
// speedup vs baseline: 1.6405x; 1.1203x over previous
#include <cuda_runtime.h>
#include <cuda_fp16.h>
#include <cstdint>
#include <cstddef>

// ============================================================================
// out = sparse @ W + b via 2:4 structured-sparse fp16 mma.sp (m16n8k32).
// Overflow (>2 nz per 4-group, ~0.37%) -> exact fp32 rank-1 corrections.
// Metadata (selector 0): lane 4q+h holds rows q (lo16) / q+8 (hi16),
// k-groups h*4..h*4+3 of the k32 chunk.
// R10: back to the proven 128x128 tile (R7); fragment-level software
// pipelining - all LDSM for both k32 chunks issued before all MMAs per kt
// (one warp convoy per kt instead of two). Coalesced corr from R9.
// ============================================================================

#define MDIM 4096
#define NDIM 4096
#define KDIM 4096

#define BM 128
#define BN 128
#define STAGES 4
#define NKT (KDIM / 64)              // 64
#define NC32 (KDIM / 32)             // 128
#define NRB (MDIM / 16)              // 256
#define A_ST 8192                    // 128 rows x 64B compressed
#define B_ST 16384                   // 128 rows x 128B
#define STAGE_BYTES 25600            // A + B + 1KB meta
#define SMEM_TOTAL (STAGES * STAGE_BYTES) // 102400

struct OvfEnt { uint32_t k; float v; };

__device__ __align__(16) __half   g_Av[(size_t)MDIM * (KDIM / 2)];
__device__ __align__(16) uint16_t g_meta16[(size_t)NC32 * NRB * 16 * 2];
__device__ __align__(16) __half   g_B[(size_t)NDIM * KDIM];
__device__ __align__(16) OvfEnt   g_ovf[(size_t)MDIM * 128 * 8];
__device__            uint8_t     g_cnt[(size_t)MDIM * 128];

// ---------------------------------------------------------------------------
__device__ __forceinline__ uint32_t h2_as_u32(__half2 h) {
    return *reinterpret_cast<uint32_t*>(&h);
}
__device__ __forceinline__ uint32_t smem_u32(const void* p) {
    uint32_t a;
    asm("{ .reg .u64 t; cvta.to.shared.u64 t, %1; cvt.u32.u64 %0, t; }" : "=r"(a) : "l"(p));
    return a;
}
__device__ __forceinline__ void cp_async16(uint32_t dst, const void* src) {
    asm volatile("cp.async.cg.shared.global [%0], [%1], 16;" :: "r"(dst), "l"(src));
}

#define LDSM_X4(r, addr)                                                         \
    asm volatile("ldmatrix.sync.aligned.m8n8.x4.shared.b16 {%0,%1,%2,%3}, [%4];" \
                 : "=r"((r)[0]), "=r"((r)[1]), "=r"((r)[2]), "=r"((r)[3])        \
                 : "r"(addr))

__device__ __forceinline__ void mma_sp(float* c, const uint32_t* a, uint32_t b0,
                                       uint32_t b1, uint32_t b2, uint32_t b3,
                                       uint32_t e) {
    asm volatile(
        "mma.sp::ordered_metadata.sync.aligned.m16n8k32.row.col.f32.f16.f16.f32 "
        "{%0,%1,%2,%3}, {%4,%5,%6,%7}, {%8,%9,%10,%11}, {%0,%1,%2,%3}, %12, 0x0;"
        : "+f"(c[0]), "+f"(c[1]), "+f"(c[2]), "+f"(c[3])
        : "r"(a[0]), "r"(a[1]), "r"(a[2]), "r"(a[3]),
          "r"(b0), "r"(b1), "r"(b2), "r"(b3), "r"(e));
}

// ---------------------------------------------------------------------------
// pack_x_sparse (known-good)
// ---------------------------------------------------------------------------
__global__ void pack_x_sparse(const float* __restrict__ x) {
    int t = blockIdx.x * 256 + threadIdx.x;
    int row = t >> 7, chunk = t & 127;
    const float* src = x + (size_t)row * KDIM + chunk * 32;

    float vals[16];
    uint32_t meta = 0;
    OvfEnt ov[8];
    int no = 0;

#pragma unroll
    for (int g = 0; g < 8; ++g) {
        float4 q = *reinterpret_cast<const float4*>(src + g * 4);
        float v[4] = {q.x, q.y, q.z, q.w};
        int i0 = -1, i1 = -1;
#pragma unroll
        for (int p = 0; p < 4; ++p) {
            if (v[p] != 0.0f) {
                if (i0 < 0) i0 = p;
                else if (i1 < 0) i1 = p;
                else if (no < 8) { ov[no].k = chunk * 32 + g * 4 + p; ov[no].v = v[p]; ++no; }
            }
        }
        if (i0 < 0) { i0 = 0; i1 = 1; }
        else if (i1 < 0) {
            if (i0 < 3) i1 = i0 + 1;
            else { i0 = 2; i1 = 3; }
        }
        vals[2 * g]     = v[i0];
        vals[2 * g + 1] = v[i1];
        meta |= (uint32_t)(i0 | (i1 << 2)) << (4 * g);
    }

    uint32_t h[8];
#pragma unroll
    for (int j = 0; j < 8; ++j)
        h[j] = h2_as_u32(__floats2half2_rn(vals[2 * j], vals[2 * j + 1]));
    __half* dst = &g_Av[(size_t)row * (KDIM / 2) + chunk * 16];
    *reinterpret_cast<uint4*>(dst)     = make_uint4(h[0], h[1], h[2], h[3]);
    *reinterpret_cast<uint4*>(dst + 8) = make_uint4(h[4], h[5], h[6], h[7]);

    {
        int rb = row >> 4, q = row & 7, part = (row >> 3) & 1;
        size_t base = (((size_t)chunk * NRB + rb) * 16 + q * 2) * 2 + part;
        g_meta16[base]     = (uint16_t)(meta & 0xFFFF);
        g_meta16[base + 2] = (uint16_t)(meta >> 16);
    }

    g_cnt[(size_t)row * 128 + chunk] = (uint8_t)no;
    OvfEnt* oslot = &g_ovf[((size_t)row * 128 + chunk) * 8];
    for (int s = 0; s < no; ++s) oslot[s] = ov[s];
}

// ---------------------------------------------------------------------------
// pack_w (known-good)
// ---------------------------------------------------------------------------
__global__ void pack_w_kernel(const float* __restrict__ w) {
    __shared__ float tile[64][65];
    int nb = blockIdx.x >> 6, kb = blockIdx.x & 63;
    int tid = threadIdx.x;
#pragma unroll
    for (int i = 0; i < 16; ++i) {
        int lin = tid + i * 256;
        int kk = lin >> 6, nn = lin & 63;
        tile[kk][nn] = w[(size_t)(kb * 64 + kk) * NDIM + (nb * 64 + nn)];
    }
    __syncthreads();
    int nn = tid >> 2;
    int kq = (tid & 3) * 16;
    __half* dst = &g_B[(size_t)(nb * 64 + nn) * KDIM + kb * 64 + kq];
    uint32_t r[8];
#pragma unroll
    for (int j = 0; j < 8; ++j)
        r[j] = h2_as_u32(__floats2half2_rn(tile[kq + 2 * j][nn], tile[kq + 2 * j + 1][nn]));
    *reinterpret_cast<uint4*>(dst)     = make_uint4(r[0], r[1], r[2], r[3]);
    *reinterpret_cast<uint4*>(dst + 8) = make_uint4(r[4], r[5], r[6], r[7]);
}

// ---------------------------------------------------------------------------
// GEMM: 128x128 tile, 8 warps (2m x 4n bands of 64x32), k64 per kt,
// 4-stage cp.async pipeline, fragment-level software pipelining.
// ---------------------------------------------------------------------------
__device__ __forceinline__ void load_stage(uint32_t sb, int stage, int bm, int bn,
                                           int tid, int kt) {
    uint32_t aT = sb + stage * STAGE_BYTES;
    uint32_t bT = aT + A_ST;
    uint32_t mT = aT + A_ST + B_ST;

    // A: 512 cp16
    {
        int row = tid & 127;
        int c0 = (tid >> 7) * 2;
        const char* src = (const char*)&g_Av[(size_t)(bm * BM + row) * (KDIM / 2)] + kt * 64;
        int swz = (row >> 1) & 3;
#pragma unroll
        for (int j = 0; j < 2; ++j) {
            int c = c0 + j;
            cp_async16(aT + row * 64 + ((c ^ swz) * 16), src + c * 16);
        }
    }
    // B: 1024 cp16
    {
        int row = tid >> 1;
        int c0 = (tid & 1) * 4;
        const char* src = (const char*)&g_B[(size_t)(bn * BN + row) * KDIM] + kt * 128;
        int swz = row & 7;
#pragma unroll
        for (int j = 0; j < 4; ++j) {
            int c = c0 + j;
            cp_async16(bT + row * 128 + ((c ^ swz) * 16), src + c * 16);
        }
    }
    // meta: 64 cp16
    if (tid < 64) {
        int cl = tid >> 5;
        int rbl = (tid >> 2) & 7;
        int w4 = tid & 3;
        const char* src = (const char*)&g_meta16[
            (((size_t)(kt * 2 + cl) * NRB + bm * 8 + rbl) * 16 + w4 * 4) * 2];
        cp_async16(mT + cl * 512 + rbl * 64 + w4 * 16, src);
    }
}

__global__ void __launch_bounds__(256)
gemm_kernel(const float* __restrict__ bias, float* __restrict__ out) {
    extern __shared__ unsigned char smem[];
    const uint32_t sb = smem_u32(smem);
    const int tid = threadIdx.x, wid = tid >> 5, lane = tid & 31;
    const int bm = blockIdx.x & 31, bn = blockIdx.x >> 5;
    const int wm = (wid >> 2) * 64, wn = (wid & 3) * 32;

#pragma unroll
    for (int s = 0; s < STAGES - 1; ++s) {
        load_stage(sb, s, bm, bn, tid, s);
        asm volatile("cp.async.commit_group;" ::: "memory");
    }

    float c[4][4][4];
#pragma unroll
    for (int i = 0; i < 4; ++i)
#pragma unroll
        for (int j = 0; j < 4; ++j)
#pragma unroll
            for (int k = 0; k < 4; ++k) c[i][j][k] = 0.f;

    const int a_row = wm + (lane & 15);                      // + mi*16
    const int a_kh = lane >> 4;
    const int b_row = wn + (lane & 7) + ((lane >> 4) << 3);  // + njb*16
    const int b_kh = (lane >> 3) & 1;
    const int m_word = ((lane >> 2) * 2 + (lane & 1)) * 4;
    const int rb0 = (wid >> 2) * 4;                          // + mi

    for (int kt = 0; kt < NKT; ++kt) {
        const int stage = kt & (STAGES - 1);
        asm volatile("cp.async.wait_group %0;" :: "n"(STAGES - 2) : "memory");
        __syncthreads();
        if (kt + STAGES - 1 < NKT)
            load_stage(sb, (kt + STAGES - 1) & (STAGES - 1), bm, bn, tid, kt + STAGES - 1);
        asm volatile("cp.async.commit_group;" ::: "memory");

        const uint32_t aT = sb + stage * STAGE_BYTES;
        const uint32_t bT = aT + A_ST;
        const uint32_t mT = aT + A_ST + B_ST;

        // ---- fragment loads for BOTH k32 chunks first (one convoy per kt) --
        uint32_t e[2][4];
        uint32_t a[2][4][4];
        uint32_t b[2][2][2][4];  // [chunk][njb][half][reg]
#pragma unroll
        for (int chunk = 0; chunk < 2; ++chunk) {
#pragma unroll
            for (int mi = 0; mi < 4; ++mi)
                asm volatile("ld.shared.b32 %0, [%1];"
                             : "=r"(e[chunk][mi])
                             : "r"(mT + chunk * 512 + (rb0 + mi) * 64 + m_word));
#pragma unroll
            for (int mi = 0; mi < 4; ++mi) {
                int row = a_row + mi * 16;
                int ch = chunk * 2 + a_kh;
                uint32_t addr = aT + row * 64 + ((ch ^ ((row >> 1) & 3)) * 16);
                LDSM_X4(a[chunk][mi], addr);
            }
#pragma unroll
            for (int njb = 0; njb < 2; ++njb)
#pragma unroll
                for (int h = 0; h < 2; ++h) {
                    int row = b_row + njb * 16;
                    int ch = (chunk * 2 + h) * 2 + b_kh;
                    uint32_t addr = bT + row * 128 + ((ch ^ (row & 7)) * 16);
                    LDSM_X4(b[chunk][njb][h], addr);
                }
        }
        // ---- all MMAs ------------------------------------------------------
#pragma unroll
        for (int chunk = 0; chunk < 2; ++chunk)
#pragma unroll
            for (int mi = 0; mi < 4; ++mi)
#pragma unroll
                for (int ni = 0; ni < 4; ++ni) {
                    int njb = ni >> 1, sub = (ni & 1) * 2;
                    mma_sp(c[mi][ni], a[chunk][mi],
                           b[chunk][njb][0][sub], b[chunk][njb][0][sub + 1],
                           b[chunk][njb][1][sub], b[chunk][njb][1][sub + 1],
                           e[chunk][mi]);
                }
    }

    // Epilogue
    const int g = lane >> 2, t2 = (lane & 3) * 2;
#pragma unroll
    for (int mi = 0; mi < 4; ++mi) {
        const int m = bm * BM + wm + mi * 16 + g;
#pragma unroll
        for (int ni = 0; ni < 4; ++ni) {
            const int n = bn * BN + wn + ni * 8 + t2;
            const float b0 = bias[n], b1 = bias[n + 1];
            float2 v0 = {c[mi][ni][0] + b0, c[mi][ni][1] + b1};
            float2 v1 = {c[mi][ni][2] + b0, c[mi][ni][3] + b1};
            *reinterpret_cast<float2*>(out + (size_t)m * NDIM + n) = v0;
            *reinterpret_cast<float2*>(out + (size_t)(m + 8) * NDIM + n) = v1;
        }
    }
}

// ---------------------------------------------------------------------------
// Correction: block per row; warp 0 gathers overflow list; 256 threads RMW
// with warp-contiguous float4 accesses (n = tid*4 + j*1024).
// ---------------------------------------------------------------------------
__global__ void __launch_bounds__(256)
corr_kernel(const float* __restrict__ w, float* __restrict__ out) {
    __shared__ uint32_t sk[64];
    __shared__ float sv[64];
    __shared__ int stot;
    const int m = blockIdx.x;
    const int tid = threadIdx.x, lane = tid & 31;

    if (tid < 32) {
        uint32_t cbytes = *(const uint32_t*)(g_cnt + (size_t)m * 128 + lane * 4);
        int local = (cbytes & 0xFF) + ((cbytes >> 8) & 0xFF) + ((cbytes >> 16) & 0xFF) +
                    (cbytes >> 24);
        int pre = local;
#pragma unroll
        for (int off = 1; off < 32; off <<= 1) {
            int nval = __shfl_up_sync(0xFFFFFFFFu, pre, off);
            if (lane >= off) pre += nval;
        }
        int excl = pre - local;
        int total = __shfl_sync(0xFFFFFFFFu, pre, 31);
        if (total > 64) total = 64;
        if (local) {
            int pos = excl;
            for (int j = 0; j < 4; ++j) {
                int cc = (cbytes >> (8 * j)) & 0xFF;
                const OvfEnt* e = &g_ovf[((size_t)m * 128 + lane * 4 + j) * 8];
                for (int s = 0; s < cc && pos < 64; ++s, ++pos) {
                    sk[pos] = e[s].k;
                    sv[pos] = e[s].v;
                }
            }
        }
        if (lane == 31) stot = total;
    }
    __syncthreads();
    const int total = stot;
    if (!total) return;

    float4 o[4];
#pragma unroll
    for (int j = 0; j < 4; ++j)
        o[j] = *reinterpret_cast<float4*>(out + (size_t)m * NDIM + tid * 4 + j * 1024);
    for (int ei = 0; ei < total; ++ei) {
        const uint32_t k = sk[ei];
        const float v = sv[ei];
        const float* wr = w + (size_t)k * NDIM;
#pragma unroll
        for (int j = 0; j < 4; ++j) {
            float4 ww = *reinterpret_cast<const float4*>(wr + tid * 4 + j * 1024);
            o[j].x += v * ww.x; o[j].y += v * ww.y;
            o[j].z += v * ww.z; o[j].w += v * ww.w;
        }
    }
#pragma unroll
    for (int j = 0; j < 4; ++j)
        *reinterpret_cast<float4*>(out + (size_t)m * NDIM + tid * 4 + j * 1024) = o[j];
}

// ---------------------------------------------------------------------------
extern "C" void kernel_launch(void* const* d_in, const int* in_sizes, int n_in,
                              void* d_out, int out_size) {
    const float* x = (const float*)d_in[0];
    const float* w = (const float*)d_in[1];
    const float* b = (const float*)d_in[2];
    float* out = (float*)d_out;

    cudaFuncSetAttribute(gemm_kernel, cudaFuncAttributeMaxDynamicSharedMemorySize,
                         SMEM_TOTAL);

    pack_x_sparse<<<(MDIM * 128) / 256, 256>>>(x);
    pack_w_kernel<<<(KDIM / 64) * (NDIM / 64), 256>>>(w);
    gemm_kernel<<<(MDIM / BM) * (NDIM / BN), 256, SMEM_TOTAL>>>(b, out);
    corr_kernel<<<MDIM, 256>>>(w, out);
}